// round 15
// baseline (speedup 1.0000x reference)
#include <cuda_runtime.h>
#include <cuda_bf16.h>
#include <cstdint>

// Problem constants
#define OFFSET   2
#define EPSILONF 0.01f
#define NUM_EMB  2050      // 2048 + OFFSET
#define EMB_D    2048
#define NUM_PAR  8
#define BATCH    8
#define SEQ      2048

// ---------------------------------------------------------------------------
// Fused kernel, two s-positions per block (R12 structure).
//
// Block = (s_pair i, b), b in LOW bits of blockIdx.x (cross-batch L2 reuse
// in-wave). 1024 threads: warps 0..15 stream row s0=2i, warps 16..31 stream
// row s1=2i+1. One reduce serves both rows:
//   cumsum[s0] = cumsum[s1] - mask[s1], both masks in the same int4 word.
//
// R15 delta: broadcast sum of the 16 warp partials reads shared as 4x int4
// LDS.128 instead of 16 scalar LDS -> 4x fewer LDS accesses on the
// critical path before the first gather load issues.
//
// Main loop at the compulsory-traffic floor (R8 A/B: __stcs neutral):
// 1 weight load, 8 independent mu loads, 8 plain float4 stores.
// Session evidence (R10/R12/R14 all within 0.2%): limiter is the
// write-dominated HBM stream ceiling (~6.26 TB/s effective).
// ---------------------------------------------------------------------------
__global__ __launch_bounds__(1024, 2)
void fused_embed_kernel(const int4*   __restrict__ mask4,
                        const float4* __restrict__ weight4,
                        const float4* __restrict__ mu4,
                        float4*       __restrict__ out4)
{
    const int bid  = blockIdx.x;            // i*BATCH + b
    const int i    = bid >> 3;              // s pair index, 0..1023
    const int b    = bid & 7;
    const int t    = threadIdx.x;           // 0..1023
    const int half = t >> 9;                // 0 -> row s0, 1 -> row s1
    const int tt   = t & 511;               // d/4 within row
    const int lane = t & 31;
    const int wid  = t >> 5;                // 0..31

    const int s1 = 2 * i + 1;               // odd
    const int s  = 2 * i + half;            // this half's row

    __shared__ __align__(16) int sh_warp[16];
    __shared__ int sh_m0, sh_m1;

    // ---- one reduce: cumsum(mask[b])[s1], computed by warps 0..15 ----
    const int owner = s1 >> 2;               // thread (in half 0) owning s1
    int partial = 0;
    if (half == 0 && tt <= owner) {
        const int4 mv = __ldg(&mask4[b * (SEQ / 4) + tt]);   // elems 4tt..4tt+3
        if (tt < owner) {
            partial = mv.x + mv.y + mv.z + mv.w;
        } else {
            const int j1 = s1 & 3;           // 1 or 3 (s1 odd)
            partial = mv.x + mv.y;           // j1 >= 1 always
            if (j1 == 3) partial += mv.z + mv.w;
            // mask[s0], mask[s1] are adjacent in this same word
            if (j1 == 1) { sh_m0 = mv.x; sh_m1 = mv.y; }
            else         { sh_m0 = mv.z; sh_m1 = mv.w; }
        }
    }

    partial = __reduce_add_sync(0xFFFFFFFFu, partial);       // REDUX.SUM
    if (lane == 0 && wid < 16) sh_warp[wid] = partial;
    __syncthreads();

    // Broadcast sum of 16 partials, vectorized: 4x LDS.128 per thread
    int incl1 = 0;                                           // cumsum[s1]
    {
        const int4* sw4 = reinterpret_cast<const int4*>(sh_warp);
        #pragma unroll
        for (int k = 0; k < 4; k++) {
            const int4 v = sw4[k];
            incl1 += v.x + v.y + v.z + v.w;
        }
    }

    const int m0 = sh_m0, m1 = sh_m1;
    const int incl0 = incl1 - m1;                            // cumsum[s0]
    // pos = incl*m - 1 + OFFSET = incl*m + 1
    const int pos = half ? (incl1 * m1 + 1) : (incl0 * m0 + 1);

    // ---- gather + axpy ----
    const int    D4        = EMB_D / 4;                  // 512
    const size_t p_stride  = (size_t)BATCH * SEQ * D4;   // float4s per out p-slab
    const size_t mu_stride = (size_t)NUM_EMB * D4;       // float4s per mu p-slab

    const size_t row    = (size_t)pos * D4 + tt;
    const float4 w      = __ldg(&weight4[row]);
    const size_t out_bs = ((size_t)b * SEQ + s) * D4 + tt;

    #pragma unroll
    for (int p = 0; p < NUM_PAR; p++) {
        const float4 m = __ldg(&mu4[(size_t)p * mu_stride + row]);
        float4 o;
        o.x = fmaf(EPSILONF, m.x, w.x);
        o.y = fmaf(EPSILONF, m.y, w.y);
        o.z = fmaf(EPSILONF, m.z, w.z);
        o.w = fmaf(EPSILONF, m.w, w.w);
        out4[(size_t)p * p_stride + out_bs] = o;
    }
}

// ---------------------------------------------------------------------------
// Launch
// Inputs (metadata order): attention_mask (int), past_key_values_length (0),
//                          weight (f32), mu (f32)
// Output: float32, (NUM_PAR, BATCH, SEQ, EMB_D)
// ---------------------------------------------------------------------------
extern "C" void kernel_launch(void* const* d_in, const int* in_sizes, int n_in,
                              void* d_out, int out_size)
{
    const int4*   mask   = (const int4*)d_in[0];
    // d_in[1] = past_key_values_length, always 0 in this problem
    const float4* weight = (const float4*)d_in[2];
    const float4* mu     = (const float4*)d_in[3];
    float4*       out    = (float4*)d_out;

    fused_embed_kernel<<<(SEQ / 2) * BATCH, 1024>>>(mask, weight, mu, out);
}

// round 16
// speedup vs baseline: 1.0109x; 1.0109x over previous
#include <cuda_runtime.h>
#include <cuda_bf16.h>
#include <cstdint>

// Problem constants
#define OFFSET   2
#define EPSILONF 0.01f
#define NUM_EMB  2050      // 2048 + OFFSET
#define EMB_D    2048
#define NUM_PAR  8
#define BATCH    8
#define SEQ      2048

// ---------------------------------------------------------------------------
// Fused kernel, two s-positions per block. (R14 — best measured variant,
// reverted from the R15 LDS.128 experiment which measured -1.9us.)
//
// Block = (s_pair i, b), b in LOW bits of blockIdx.x (cross-batch L2 reuse
// in-wave, established R2/R5). 1024 threads: warps 0..15 stream row s0=2i,
// warps 16..31 stream row s1=2i+1.
//
// Prologue amortization: cumsum[s1] determines BOTH positions
// (cumsum[s0] = cumsum[s1] - mask[s1]), and since s1 is odd, mask[s0] and
// mask[s1] live in the same int4 word. One reduce serves 2 rows.
//
// Main loop at the compulsory-traffic floor (R8 A/B: __stcs neutral):
// 1 weight load, 8 independent mu loads, 8 plain float4 stores.
// Session evidence: limiter is the write-dominated HBM stream ceiling
// (~6.26 TB/s effective on the 1.074 GB compulsory output).
// ---------------------------------------------------------------------------
__global__ __launch_bounds__(1024, 2)
void fused_embed_kernel(const int4*   __restrict__ mask4,
                        const float4* __restrict__ weight4,
                        const float4* __restrict__ mu4,
                        float4*       __restrict__ out4)
{
    const int bid  = blockIdx.x;            // i*BATCH + b
    const int i    = bid >> 3;              // s pair index, 0..1023
    const int b    = bid & 7;
    const int t    = threadIdx.x;           // 0..1023
    const int half = t >> 9;                // 0 -> row s0, 1 -> row s1
    const int tt   = t & 511;               // d/4 within row
    const int lane = t & 31;
    const int wid  = t >> 5;                // 0..31

    const int s1 = 2 * i + 1;               // odd
    const int s  = 2 * i + half;            // this half's row

    __shared__ int sh_warp[16];
    __shared__ int sh_m0, sh_m1;

    // ---- one reduce: cumsum(mask[b])[s1], done by warps 0..15 ----
    const int owner = s1 >> 2;               // thread (in half 0) owning s1
    int partial = 0;
    if (half == 0 && tt <= owner) {
        const int4 mv = __ldg(&mask4[b * (SEQ / 4) + tt]);   // elems 4tt..4tt+3
        if (tt < owner) {
            partial = mv.x + mv.y + mv.z + mv.w;
        } else {
            const int j1 = s1 & 3;           // 1 or 3 (s1 odd)
            partial = mv.x + mv.y;           // j1 >= 1 always
            if (j1 == 3) partial += mv.z + mv.w;
            // mask[s0], mask[s1] are adjacent in this same word
            if (j1 == 1) { sh_m0 = mv.x; sh_m1 = mv.y; }
            else         { sh_m0 = mv.z; sh_m1 = mv.w; }
        }
    }

    partial = __reduce_add_sync(0xFFFFFFFFu, partial);       // REDUX.SUM
    if (lane == 0 && wid < 16) sh_warp[wid] = partial;
    __syncthreads();

    int incl1 = 0;                                           // cumsum[s1]
    #pragma unroll
    for (int k = 0; k < 16; k++) incl1 += sh_warp[k];        // broadcast LDS

    const int m0 = sh_m0, m1 = sh_m1;
    const int incl0 = incl1 - m1;                            // cumsum[s0]
    // pos = incl*m - 1 + OFFSET = incl*m + 1
    const int pos = half ? (incl1 * m1 + 1) : (incl0 * m0 + 1);

    // ---- gather + axpy ----
    const int    D4        = EMB_D / 4;                  // 512
    const size_t p_stride  = (size_t)BATCH * SEQ * D4;   // float4s per out p-slab
    const size_t mu_stride = (size_t)NUM_EMB * D4;       // float4s per mu p-slab

    const size_t row    = (size_t)pos * D4 + tt;
    const float4 w      = __ldg(&weight4[row]);
    const size_t out_bs = ((size_t)b * SEQ + s) * D4 + tt;

    #pragma unroll
    for (int p = 0; p < NUM_PAR; p++) {
        const float4 m = __ldg(&mu4[(size_t)p * mu_stride + row]);
        float4 o;
        o.x = fmaf(EPSILONF, m.x, w.x);
        o.y = fmaf(EPSILONF, m.y, w.y);
        o.z = fmaf(EPSILONF, m.z, w.z);
        o.w = fmaf(EPSILONF, m.w, w.w);
        out4[(size_t)p * p_stride + out_bs] = o;
    }
}

// ---------------------------------------------------------------------------
// Launch
// Inputs (metadata order): attention_mask (int), past_key_values_length (0),
//                          weight (f32), mu (f32)
// Output: float32, (NUM_PAR, BATCH, SEQ, EMB_D)
// ---------------------------------------------------------------------------
extern "C" void kernel_launch(void* const* d_in, const int* in_sizes, int n_in,
                              void* d_out, int out_size)
{
    const int4*   mask   = (const int4*)d_in[0];
    // d_in[1] = past_key_values_length, always 0 in this problem
    const float4* weight = (const float4*)d_in[2];
    const float4* mu     = (const float4*)d_in[3];
    float4*       out    = (float4*)d_out;

    fused_embed_kernel<<<(SEQ / 2) * BATCH, 1024>>>(mask, weight, mu, out);
}